// round 2
// baseline (speedup 1.0000x reference)
#include <cuda_runtime.h>
#include <math.h>
#include <stdint.h>

#define BATCH    2048
#define IN_DIM   2048
#define POOLN    32768
#define HIDN     1024
#define MAXP     8192
#define MINP     512

// ---------------- scratch (device globals: no allocations allowed) ----------
__device__ float g_c1[BATCH * 128];
__device__ float g_h[BATCH * HIDN];
__device__ float g_scores[(size_t)BATCH * POOLN];   // 256 MB
__device__ float g_comp[BATCH];
__device__ int   g_budget;

// ---------------- packed f32x2 helpers (FFMA2 path, bitwise == scalar FMA) --
__device__ __forceinline__ unsigned long long pk2(float lo, float hi) {
    unsigned long long r;
    asm("mov.b64 %0, {%1, %2};"
        : "=l"(r) : "r"(__float_as_uint(lo)), "r"(__float_as_uint(hi)));
    return r;
}
__device__ __forceinline__ void fma2(unsigned long long& d,
                                     unsigned long long a,
                                     unsigned long long b) {
    asm("fma.rn.f32x2 %0, %1, %2, %3;" : "=l"(d) : "l"(a), "l"(b), "l"(d));
}
__device__ __forceinline__ float2 upk2(unsigned long long v) {
    unsigned lo, hi;
    asm("mov.b64 {%0, %1}, %2;" : "=r"(lo), "=r"(hi) : "l"(v));
    return make_float2(__uint_as_float(lo), __uint_as_float(hi));
}

// ---------------- fp32 tiled GEMM (FFMA2): C = epi(A[MxK] @ B[KxN]) ---------
// epi==0 : C = relu(acc + bias[col])
// epi==1 : C = (acc + bias[col]) + noise[row*N+col]*0.1f   (roundings separate)
// Accumulation: per output element, sequential ascending-k fused FMA (RN) —
// bitwise identical to the scalar-FFMA version and to cuBLAS SIMT sgemm.
__global__ void __launch_bounds__(256, 2) sgemm128(
    const float* __restrict__ A, const float* __restrict__ B,
    const float* __restrict__ bias, const float* __restrict__ noise,
    float* __restrict__ C, int M, int N, int K, int epi)
{
    __shared__ float As[16][128];
    __shared__ float Bs[16][128];

    const int bx = blockIdx.x, by = blockIdx.y;
    const int tid = threadIdx.x;
    const int tn = tid & 15;        // 0..15  (col group)
    const int tm = tid >> 4;        // 0..15  (row group)

    const float* Ab = A + (size_t)by * 128 * K;
    const float* Bb = B + (size_t)bx * 128;

    // acc2[p][j] = (C[2p][j], C[2p+1][j]) packed f32x2
    unsigned long long acc2[4][8];
#pragma unroll
    for (int p = 0; p < 4; p++)
#pragma unroll
        for (int j = 0; j < 8; j++) acc2[p][j] = 0ULL;

    for (int k0 = 0; k0 < K; k0 += 16) {
        // load A tile 128x16 (each thread: 2 float4)
#pragma unroll
        for (int l = 0; l < 2; l++) {
            int pos = tid * 2 + l;           // 0..511
            int r = pos >> 2, c4 = pos & 3;  // 128 rows x 4 float4
            float4 v = *(const float4*)(Ab + (size_t)r * K + k0 + c4 * 4);
            As[c4 * 4 + 0][r] = v.x;
            As[c4 * 4 + 1][r] = v.y;
            As[c4 * 4 + 2][r] = v.z;
            As[c4 * 4 + 3][r] = v.w;
        }
        // load B tile 16x128 (each thread: 2 float4, fully coalesced)
#pragma unroll
        for (int l = 0; l < 2; l++) {
            int pos = tid * 2 + l;            // 0..511
            int r = pos >> 5, c4 = pos & 31;  // 16 rows x 32 float4
            *(float4*)&Bs[r][c4 * 4] = *(const float4*)(Bb + (size_t)(k0 + r) * N + c4 * 4);
        }
        __syncthreads();

#pragma unroll
        for (int k = 0; k < 16; k++) {
            const float4* a4 = (const float4*)&As[k][tm * 8];
            const float4* b4 = (const float4*)&Bs[k][tn * 8];
            float4 av0 = a4[0], av1 = a4[1];
            float4 bv0 = b4[0], bv1 = b4[1];
            unsigned long long ap[4];
            ap[0] = pk2(av0.x, av0.y);
            ap[1] = pk2(av0.z, av0.w);
            ap[2] = pk2(av1.x, av1.y);
            ap[3] = pk2(av1.z, av1.w);
            float bsv[8];
            bsv[0]=bv0.x; bsv[1]=bv0.y; bsv[2]=bv0.z; bsv[3]=bv0.w;
            bsv[4]=bv1.x; bsv[5]=bv1.y; bsv[6]=bv1.z; bsv[7]=bv1.w;
#pragma unroll
            for (int j = 0; j < 8; j++) {
                unsigned long long bd = pk2(bsv[j], bsv[j]);
                fma2(acc2[0][j], ap[0], bd);
                fma2(acc2[1][j], ap[1], bd);
                fma2(acc2[2][j], ap[2], bd);
                fma2(acc2[3][j], ap[3], bd);
            }
        }
        __syncthreads();
    }

#pragma unroll
    for (int p = 0; p < 4; p++) {
#pragma unroll
        for (int j = 0; j < 8; j++) {
            float2 cv = upk2(acc2[p][j]);
            int col = bx * 128 + tn * 8 + j;
#pragma unroll
            for (int h = 0; h < 2; h++) {
                int row = by * 128 + tm * 8 + 2 * p + h;
                float v = (h == 0) ? cv.x : cv.y;
                if (epi == 0) {
                    v = fmaxf(__fadd_rn(v, bias[col]), 0.0f);
                } else {
                    v = __fadd_rn(v, bias[col]);
                    float nz = __fmul_rn(noise[(size_t)row * N + col], 0.1f);
                    v = __fadd_rn(v, nz);
                }
                C[(size_t)row * N + col] = v;
            }
        }
    }
}

// ---------------- comp stage 2: sigmoid(c1 @ W2c + b2c) ----------------------
__global__ void comp_kernel(const float* __restrict__ W2c,
                            const float* __restrict__ b2c,
                            float* __restrict__ out_comp)
{
    int row  = blockIdx.x * 8 + (threadIdx.x >> 5);
    int lane = threadIdx.x & 31;
    float p = 0.0f;
#pragma unroll
    for (int t = lane; t < 128; t += 32) p += g_c1[row * 128 + t] * W2c[t];
#pragma unroll
    for (int o = 16; o > 0; o >>= 1) p += __shfl_down_sync(0xffffffffu, p, o);
    if (lane == 0) {
        float z = p + b2c[0];
        float c = 1.0f / (1.0f + expf(-z));
        g_comp[row]  = c;
        out_comp[row] = c;
    }
}

// ---------------- budget --------------------------------------------------
__global__ void budget_kernel(float* __restrict__ out_budget)
{
    __shared__ float ws[32];
    int tid = threadIdx.x;
    float s = g_comp[tid] + g_comp[tid + 1024];
#pragma unroll
    for (int o = 16; o > 0; o >>= 1) s += __shfl_down_sync(0xffffffffu, s, o);
    if ((tid & 31) == 0) ws[tid >> 5] = s;
    __syncthreads();
    if (tid < 32) {
        float v = ws[tid];
#pragma unroll
        for (int o = 16; o > 0; o >>= 1) v += __shfl_down_sync(0xffffffffu, v, o);
        if (tid == 0) {
            float mean  = v / 2048.0f;
            float scale = mean * mean;                 // EXP = 2.0
            float t = 512.0f + 7680.0f * scale;
            int b = (int)floorf(t);
            if (b < MINP) b = MINP;
            if (b > MAXP) b = MAXP;
            g_budget = b;
            out_budget[0] = (float)b;
        }
    }
}

// ---------------- top-k + softmax -----------------------------------------
__device__ __forceinline__ unsigned f2key(float s) {
    unsigned b = __float_as_uint(s);
    return (b & 0x80000000u) ? ~b : (b | 0x80000000u);   // order-preserving
}
__device__ __forceinline__ float key2f(unsigned k) {
    return __uint_as_float((k & 0x80000000u) ? (k ^ 0x80000000u) : ~k);
}

// smem: keys u32[32768] | sbuf u64[8192] | red i32[128]
#define TOPK_SMEM (131072 + 65536 + 512)

__global__ void __launch_bounds__(1024) topk_kernel(
    float* __restrict__ out_idx, float* __restrict__ out_w)
{
    extern __shared__ unsigned char smem_raw[];
    unsigned*           keys = (unsigned*)smem_raw;
    unsigned long long* sbuf = (unsigned long long*)(smem_raw + 131072);
    int*                red  = (int*)(smem_raw + 131072 + 65536);
    float*              fred = (float*)red;

    const int row = blockIdx.x;
    const int tid = threadIdx.x;
    const int warp = tid >> 5, lane = tid & 31;
    const float* srow = g_scores + (size_t)row * POOLN;

    // load + transform
    for (int j = tid; j < POOLN; j += 1024) keys[j] = f2key(srow[j]);
    __syncthreads();

    // exact k-th largest key: minimal t with count(key > t) < 8192
    unsigned lo = 0u, hi = 0xFFFFFFFFu;
    while (lo < hi) {
        unsigned mid = lo + ((hi - lo) >> 1);
        int c = 0;
#pragma unroll 8
        for (int j = tid; j < POOLN; j += 1024) c += (keys[j] > mid) ? 1 : 0;
#pragma unroll
        for (int o = 16; o > 0; o >>= 1) c += __shfl_down_sync(0xffffffffu, c, o);
        __syncthreads();
        if (tid == 0) red[0] = 0;
        __syncthreads();
        if (lane == 0) atomicAdd(&red[0], c);
        __syncthreads();
        int total = red[0];
        if (total < MAXP) hi = mid; else lo = mid + 1;
    }
    const unsigned V = lo;

    // per-thread contiguous chunk (preserves ascending idx order for ties)
    const int beg = tid * 32;
    int cgt = 0, ceq = 0;
#pragma unroll 8
    for (int j = beg; j < beg + 32; j++) {
        unsigned k = keys[j];
        cgt += (k > V); ceq += (k == V);
    }
    // block exclusive scan (warp shfl + warp totals)
    int vg = cgt, ve = ceq;
#pragma unroll
    for (int o = 1; o < 32; o <<= 1) {
        int ng = __shfl_up_sync(0xffffffffu, vg, o);
        int ne = __shfl_up_sync(0xffffffffu, ve, o);
        if (lane >= o) { vg += ng; ve += ne; }
    }
    if (lane == 31) { red[2 + warp] = vg; red[34 + warp] = ve; }
    __syncthreads();
    if (tid < 32) {
        int wg = red[2 + tid], we = red[34 + tid];
#pragma unroll
        for (int o = 1; o < 32; o <<= 1) {
            int ng = __shfl_up_sync(0xffffffffu, wg, o);
            int ne = __shfl_up_sync(0xffffffffu, we, o);
            if (tid >= o) { wg += ng; we += ne; }
        }
        red[2 + tid] = wg; red[34 + tid] = we;
    }
    __syncthreads();
    int base_gt = vg - cgt + (warp ? red[2 + warp - 1] : 0);
    int base_eq = ve - ceq + (warp ? red[34 + warp - 1] : 0);
    const int count_gt = red[2 + 31];
    const int need_eq  = MAXP - count_gt;

    // scatter: all >V anywhere in [0,count_gt); ties (==V) by lowest idx into tail
    for (int j = beg; j < beg + 32; j++) {
        unsigned k = keys[j];
        if (k > V) {
            sbuf[base_gt++] = ((unsigned long long)(~k) << 32) | (unsigned)j;
        } else if (k == V) {
            int r = base_eq++;
            if (r < need_eq)
                sbuf[count_gt + r] = ((unsigned long long)(~V) << 32) | (unsigned)j;
        }
    }

    // bitonic sort ascending on (~key, idx)  => key desc, idx asc on ties
    for (int size = 2; size <= MAXP; size <<= 1) {
        for (int stride = size >> 1; stride > 0; stride >>= 1) {
            __syncthreads();
#pragma unroll
            for (int q = 0; q < 4; q++) {
                int t = tid + q * 1024;
                int pos = 2 * t - (t & (stride - 1));
                bool asc = ((pos & size) == 0);
                unsigned long long a = sbuf[pos], b = sbuf[pos + stride];
                if ((a > b) == asc) { sbuf[pos] = b; sbuf[pos + stride] = a; }
            }
        }
    }
    __syncthreads();

    // softmax over first `budget` entries
    const float s0 = key2f(~(unsigned)(sbuf[0] >> 32));
    const int budget = g_budget;
    float part = 0.0f;
    float ev[8]; int iv[8];
#pragma unroll
    for (int i = 0; i < 8; i++) {
        int p = tid + i * 1024;
        unsigned long long v = sbuf[p];
        unsigned key = ~(unsigned)(v >> 32);
        iv[i] = (int)(v & 0xFFFFFFFFu);
        float e = (p < budget) ? expf(key2f(key) - s0) : 0.0f;
        ev[i] = e;
        part += e;
    }
#pragma unroll
    for (int o = 16; o > 0; o >>= 1) part += __shfl_down_sync(0xffffffffu, part, o);
    __syncthreads();
    if (lane == 0) fred[64 + warp] = part;
    __syncthreads();
    if (tid == 0) {
        float s = 0.0f;
        for (int w = 0; w < 32; w++) s += fred[64 + w];
        fred[96] = s;
    }
    __syncthreads();
    const float denom = fred[96];

#pragma unroll
    for (int i = 0; i < 8; i++) {
        int p = tid + i * 1024;
        out_idx[(size_t)row * MAXP + p] = (float)iv[i];
        out_w  [(size_t)row * MAXP + p] = ev[i] / denom;
    }
}

// ---------------- launch -----------------------------------------------------
extern "C" void kernel_launch(void* const* d_in, const int* in_sizes, int n_in,
                              void* d_out, int out_size)
{
    const float* x    = (const float*)d_in[0];
    const float* noise= (const float*)d_in[1];
    const float* W1c  = (const float*)d_in[2];
    const float* b1c  = (const float*)d_in[3];
    const float* W2c  = (const float*)d_in[4];
    const float* b2c  = (const float*)d_in[5];
    const float* Ws1  = (const float*)d_in[6];
    const float* bs1  = (const float*)d_in[7];
    const float* Ws2  = (const float*)d_in[8];
    const float* bs2  = (const float*)d_in[9];

    float* out        = (float*)d_out;
    float* out_idx    = out;
    float* out_budget = out + (size_t)BATCH * MAXP;
    float* out_w      = out_budget + 1;
    float* out_comp   = out_w + (size_t)BATCH * MAXP;

    float *c1p, *hp, *sp;
    cudaGetSymbolAddress((void**)&c1p, g_c1);
    cudaGetSymbolAddress((void**)&hp,  g_h);
    cudaGetSymbolAddress((void**)&sp,  g_scores);

    // complexity net
    sgemm128<<<dim3(1, 16), 256>>>(x, W1c, b1c, nullptr, c1p, BATCH, 128, IN_DIM, 0);
    comp_kernel<<<256, 256>>>(W2c, b2c, out_comp);
    budget_kernel<<<1, 1024>>>(out_budget);

    // scorer
    sgemm128<<<dim3(8, 16), 256>>>(x, Ws1, bs1, nullptr, hp, BATCH, HIDN, IN_DIM, 0);
    sgemm128<<<dim3(256, 16), 256>>>(hp, Ws2, bs2, noise, sp, BATCH, POOLN, HIDN, 1);

    // top-k + softmax
    cudaFuncSetAttribute(topk_kernel, cudaFuncAttributeMaxDynamicSharedMemorySize, TOPK_SMEM);
    topk_kernel<<<BATCH, 1024, TOPK_SMEM>>>(out_idx, out_w);
}

// round 3
// speedup vs baseline: 1.1034x; 1.1034x over previous
#include <cuda_runtime.h>
#include <math.h>
#include <stdint.h>

#define BATCH    2048
#define IN_DIM   2048
#define POOLN    32768
#define HIDN     1024
#define MAXP     8192
#define MINP     512

typedef unsigned long long u64;
typedef unsigned int u32;

// ---------------- scratch (device globals: no allocations allowed) ----------
__device__ float g_c1[BATCH * 128];
__device__ float g_h[BATCH * HIDN];
__device__ float g_scores[(size_t)BATCH * POOLN];   // 256 MB
__device__ float g_comp[BATCH];
__device__ int   g_budget;

// ============================================================================
// GEMM core (scalar FFMA, sequential ascending-k: bitwise-frozen numerics)
// ============================================================================
#define GEMM_BODY(Ab, Bb, Nstride, KDIM)                                        \
    float acc[8][8];                                                            \
    _Pragma("unroll")                                                           \
    for (int i = 0; i < 8; i++)                                                 \
        _Pragma("unroll")                                                       \
        for (int j = 0; j < 8; j++) acc[i][j] = 0.0f;                           \
    for (int k0 = 0; k0 < (KDIM); k0 += 16) {                                   \
        _Pragma("unroll")                                                       \
        for (int l = 0; l < 2; l++) {                                           \
            int pos = tid * 2 + l;                                              \
            int r = pos >> 2, c4 = pos & 3;                                     \
            float4 v = *(const float4*)((Ab) + (size_t)r * (KDIM) + k0 + c4*4); \
            As[c4*4+0][r] = v.x; As[c4*4+1][r] = v.y;                           \
            As[c4*4+2][r] = v.z; As[c4*4+3][r] = v.w;                           \
        }                                                                       \
        _Pragma("unroll")                                                       \
        for (int l = 0; l < 2; l++) {                                           \
            int pos = tid * 2 + l;                                              \
            int r = pos >> 5, c4 = pos & 31;                                    \
            *(float4*)&Bs[r][c4*4] =                                            \
                *(const float4*)((Bb) + (size_t)(k0 + r) * (Nstride) + c4*4);   \
        }                                                                       \
        __syncthreads();                                                        \
        _Pragma("unroll")                                                       \
        for (int k = 0; k < 16; k++) {                                          \
            float a[8], b[8];                                                   \
            const float4* a4 = (const float4*)&As[k][tm * 8];                   \
            const float4* b4 = (const float4*)&Bs[k][tn * 8];                   \
            float4 av0 = a4[0], av1 = a4[1];                                    \
            float4 bv0 = b4[0], bv1 = b4[1];                                    \
            a[0]=av0.x; a[1]=av0.y; a[2]=av0.z; a[3]=av0.w;                     \
            a[4]=av1.x; a[5]=av1.y; a[6]=av1.z; a[7]=av1.w;                     \
            b[0]=bv0.x; b[1]=bv0.y; b[2]=bv0.z; b[3]=bv0.w;                     \
            b[4]=bv1.x; b[5]=bv1.y; b[6]=bv1.z; b[7]=bv1.w;                     \
            _Pragma("unroll")                                                   \
            for (int i = 0; i < 8; i++)                                         \
                _Pragma("unroll")                                               \
                for (int j = 0; j < 8; j++) acc[i][j] += a[i] * b[j];           \
        }                                                                       \
        __syncthreads();                                                        \
    }

// ---------------- Ws2 GEMM: scores = h @ Ws2 + bs2 + noise*0.1 --------------
__global__ void __launch_bounds__(256, 2) sgemm_scores(
    const float* __restrict__ A, const float* __restrict__ B,
    const float* __restrict__ bias, const float* __restrict__ noise,
    float* __restrict__ C)
{
    __shared__ float As[16][128];
    __shared__ float Bs[16][128];
    const int bx = blockIdx.x, by = blockIdx.y;
    const int tid = threadIdx.x;
    const int tn = tid & 15, tm = tid >> 4;
    const float* Ab = A + (size_t)by * 128 * HIDN;
    const float* Bb = B + (size_t)bx * 128;

    GEMM_BODY(Ab, Bb, POOLN, HIDN)

#pragma unroll
    for (int i = 0; i < 8; i++) {
        int row = by * 128 + tm * 8 + i;
#pragma unroll
        for (int j = 0; j < 8; j++) {
            int col = bx * 128 + tn * 8 + j;
            float v = __fadd_rn(acc[i][j], bias[col]);
            float nz = __fmul_rn(noise[(size_t)row * POOLN + col], 0.1f);
            v = __fadd_rn(v, nz);
            C[(size_t)row * POOLN + col] = v;
        }
    }
}

// ---------------- fused Ws1 + W1c GEMM: relu(x@W + b) -----------------------
// bx in [0,8): h tile (N=1024).  bx == 8: c1 tile (N=128).
__global__ void __launch_bounds__(256, 2) sgemm_fused(
    const float* __restrict__ x,
    const float* __restrict__ Ws1, const float* __restrict__ bs1,
    const float* __restrict__ W1c, const float* __restrict__ b1c)
{
    __shared__ float As[16][128];
    __shared__ float Bs[16][128];
    const int bx = blockIdx.x, by = blockIdx.y;
    const int tid = threadIdx.x;
    const int tn = tid & 15, tm = tid >> 4;

    const bool is_c1 = (bx == 8);
    const float* Bsel  = is_c1 ? W1c : Ws1;
    const float* bias  = is_c1 ? b1c : bs1;
    float*       Csel  = is_c1 ? g_c1 : g_h;
    const int    N     = is_c1 ? 128 : HIDN;
    const int    cb    = is_c1 ? 0 : bx * 128;

    const float* Ab = x + (size_t)by * 128 * IN_DIM;
    const float* Bb = Bsel + cb;

    GEMM_BODY(Ab, Bb, N, IN_DIM)

#pragma unroll
    for (int i = 0; i < 8; i++) {
        int row = by * 128 + tm * 8 + i;
#pragma unroll
        for (int j = 0; j < 8; j++) {
            int col = cb + tn * 8 + j;
            float v = fmaxf(__fadd_rn(acc[i][j], bias[col]), 0.0f);
            Csel[(size_t)row * N + col] = v;
        }
    }
}

// ---------------- comp stage 2: sigmoid(c1 @ W2c + b2c) ---------------------
__global__ void comp_kernel(const float* __restrict__ W2c,
                            const float* __restrict__ b2c,
                            float* __restrict__ out_comp)
{
    int row  = blockIdx.x * 8 + (threadIdx.x >> 5);
    int lane = threadIdx.x & 31;
    float p = 0.0f;
#pragma unroll
    for (int t = lane; t < 128; t += 32) p += g_c1[row * 128 + t] * W2c[t];
#pragma unroll
    for (int o = 16; o > 0; o >>= 1) p += __shfl_down_sync(0xffffffffu, p, o);
    if (lane == 0) {
        float z = p + b2c[0];
        float c = 1.0f / (1.0f + expf(-z));
        g_comp[row]  = c;
        out_comp[row] = c;
    }
}

// ---------------- budget ----------------------------------------------------
__global__ void budget_kernel(float* __restrict__ out_budget)
{
    __shared__ float ws[32];
    int tid = threadIdx.x;
    float s = g_comp[tid] + g_comp[tid + 1024];
#pragma unroll
    for (int o = 16; o > 0; o >>= 1) s += __shfl_down_sync(0xffffffffu, s, o);
    if ((tid & 31) == 0) ws[tid >> 5] = s;
    __syncthreads();
    if (tid < 32) {
        float v = ws[tid];
#pragma unroll
        for (int o = 16; o > 0; o >>= 1) v += __shfl_down_sync(0xffffffffu, v, o);
        if (tid == 0) {
            float mean  = v / 2048.0f;
            float scale = mean * mean;                 // EXP = 2.0
            float t = 512.0f + 7680.0f * scale;
            int b = (int)floorf(t);
            if (b < MINP) b = MINP;
            if (b > MAXP) b = MAXP;
            g_budget = b;
            out_budget[0] = (float)b;
        }
    }
}

// ============================================================================
// top-k + softmax
// ============================================================================
__device__ __forceinline__ unsigned f2key(float s) {
    unsigned b = __float_as_uint(s);
    return (b & 0x80000000u) ? ~b : (b | 0x80000000u);   // order-preserving
}
__device__ __forceinline__ float key2f(unsigned k) {
    return __uint_as_float((k & 0x80000000u) ? (k ^ 0x80000000u) : ~k);
}

// smem: keys u32[32768] | sbufA u64[8192] | hist u32[4096] | red u32[160]
// sbufB (u64[8192]) aliases keys[] (keys dead after selection scatter).
#define OFF_KEYS   0
#define OFF_SBUFA  131072
#define OFF_HIST   196608
#define OFF_RED    212992
#define TOPK_SMEM  (212992 + 640)

// block-wide exclusive scan of 4096 u32 (thread t owns [4t,4t+4)); returns total.
// h[4]/ex[4] give the thread's own values/exclusive-prefixes.
__device__ __forceinline__ u32 scan4096(u32* a, u32* red, int tid,
                                        u32 h[4], u32 ex[4])
{
    const int lane = tid & 31, warp = tid >> 5;
#pragma unroll
    for (int i = 0; i < 4; i++) h[i] = a[tid * 4 + i];
    u32 s = h[0] + h[1] + h[2] + h[3];
    u32 inc = s;
#pragma unroll
    for (int o = 1; o < 32; o <<= 1) {
        u32 n = __shfl_up_sync(0xffffffffu, inc, o);
        if (lane >= o) inc += n;
    }
    if (lane == 31) red[warp] = inc;
    __syncthreads();
    if (tid < 32) {
        u32 v = red[tid];
#pragma unroll
        for (int o = 1; o < 32; o <<= 1) {
            u32 n = __shfl_up_sync(0xffffffffu, v, o);
            if (tid >= o) v += n;
        }
        red[32 + tid] = v;
    }
    __syncthreads();
    u32 wb = (warp == 0) ? 0u : red[32 + warp - 1];
    u32 tb = wb + inc - s;
    ex[0] = tb; ex[1] = ex[0] + h[0]; ex[2] = ex[1] + h[1]; ex[3] = ex[2] + h[2];
#pragma unroll
    for (int i = 0; i < 4; i++) a[tid * 4 + i] = ex[i];
    u32 total = red[32 + 31];
    __syncthreads();
    return total;
}

__device__ __forceinline__ unsigned eqmask4(unsigned d) {
    unsigned m = 0xffffffffu;
#pragma unroll
    for (int b = 0; b < 4; b++) {
        unsigned bal = __ballot_sync(0xffffffffu, (d >> b) & 1u);
        m &= ((d >> b) & 1u) ? bal : ~bal;
    }
    return m;
}

__global__ void __launch_bounds__(1024) topk_kernel(
    float* __restrict__ out_idx, float* __restrict__ out_w)
{
    extern __shared__ unsigned char smem_raw[];
    u32* keys  = (u32*)(smem_raw + OFF_KEYS);
    u64* sbufA = (u64*)(smem_raw + OFF_SBUFA);
    u64* sbufB = (u64*)(smem_raw + OFF_KEYS);     // alias: valid after keys dead
    u32* hist  = (u32*)(smem_raw + OFF_HIST);     // also radix segcnt
    u32* red   = (u32*)(smem_raw + OFF_RED);
    float* fred = (float*)red;

    const int row = blockIdx.x;
    const int tid = threadIdx.x;
    const int warp = tid >> 5, lane = tid & 31;
    const unsigned ltm = (1u << lane) - 1u;
    const float* srow = g_scores + (size_t)row * POOLN;

    // ---- load + transform ----
    for (int j = tid; j < POOLN; j += 1024) keys[j] = f2key(srow[j]);
    __syncthreads();

    // ---- exact k-th largest key via 3-level radix histogram (12/12/8) ----
    unsigned prefix = 0;     // accumulated high bits
    u32 base_gt = 0;         // count of keys strictly greater than prefix range
#pragma unroll
    for (int lvl = 0; lvl < 3; lvl++) {
        const int lb   = (lvl < 2) ? 12 : 8;
        const int done = (lvl == 0) ? 0 : (lvl == 1 ? 12 : 24);
#pragma unroll
        for (int i = 0; i < 4; i++) hist[tid * 4 + i] = 0;
        __syncthreads();
        for (int j = tid; j < POOLN; j += 1024) {
            u32 k = keys[j];
            bool part = (done == 0) || ((k >> (32 - done)) == prefix);
            unsigned d = part ? ((k << done) >> (32 - lb)) : 0xFFFFFFFFu;
            unsigned m = __match_any_sync(0xffffffffu, d);
            if (part && (m & ltm) == 0)
                atomicAdd(&hist[d], __popc(m));
        }
        __syncthreads();
        u32 h4[4], ex4[4];
        u32 T = scan4096(hist, red, tid, h4, ex4);
#pragma unroll
        for (int i = 0; i < 4; i++) {
            u32 cg = T - ex4[i] - h4[i];           // count in level with digit > d
            if (h4[i] && base_gt + cg < MAXP && base_gt + cg + h4[i] >= MAXP) {
                red[140] = (u32)(tid * 4 + i);
                red[141] = cg;
            }
        }
        __syncthreads();
        prefix = (prefix << lb) | red[140];
        base_gt += red[141];
        __syncthreads();
    }
    const unsigned V = prefix;

    // ---- stable compaction: >V anywhere, ==V lowest-idx-first into tail ----
    const int beg = tid * 32;
    int cgt = 0, ceq = 0;
#pragma unroll 8
    for (int j = beg; j < beg + 32; j++) {
        unsigned k = keys[j];
        cgt += (k > V); ceq += (k == V);
    }
    int vg = cgt, ve = ceq;
#pragma unroll
    for (int o = 1; o < 32; o <<= 1) {
        int ng = __shfl_up_sync(0xffffffffu, vg, o);
        int ne = __shfl_up_sync(0xffffffffu, ve, o);
        if (lane >= o) { vg += ng; ve += ne; }
    }
    if (lane == 31) { red[2 + warp] = (u32)vg; red[34 + warp] = (u32)ve; }
    __syncthreads();
    if (tid < 32) {
        int wg = (int)red[2 + tid], we = (int)red[34 + tid];
#pragma unroll
        for (int o = 1; o < 32; o <<= 1) {
            int ng = __shfl_up_sync(0xffffffffu, wg, o);
            int ne = __shfl_up_sync(0xffffffffu, we, o);
            if (tid >= o) { wg += ng; we += ne; }
        }
        red[2 + tid] = (u32)wg; red[34 + tid] = (u32)we;
    }
    __syncthreads();
    int bgt = vg - cgt + (warp ? (int)red[2 + warp - 1] : 0);
    int beq = ve - ceq + (warp ? (int)red[34 + warp - 1] : 0);
    const int count_gt = (int)red[2 + 31];
    const int need_eq  = MAXP - count_gt;

    for (int j = beg; j < beg + 32; j++) {
        unsigned k = keys[j];
        if (k > V) {
            sbufA[bgt++] = ((u64)(~k) << 32) | (unsigned)j;
        } else if (k == V) {
            int r = beq++;
            if (r < need_eq)
                sbufA[count_gt + r] = ((u64)(~V) << 32) | (unsigned)j;
        }
    }
    __syncthreads();
    // keys[] dead from here; sbufB / segcnt reuse its space.

    // ---- stable LSD radix sort: ascending on ~key (== key desc), 8x4 bits --
    u64* src = sbufA;
    u64* dst = sbufB;
#pragma unroll 1
    for (int p = 0; p < 8; p++) {
        const int shift = 32 + 4 * p;
#pragma unroll
        for (int i = 0; i < 4; i++) hist[tid * 4 + i] = 0;
        __syncthreads();
#pragma unroll 1
        for (int e = 0; e < 8; e++) {
            u64 v = src[e * 1024 + tid];
            unsigned d = (unsigned)(v >> shift) & 15u;
            unsigned m = eqmask4(d);
            if ((m & ltm) == 0)
                hist[d * 256 + e * 32 + warp] = (u32)__popc(m);
        }
        __syncthreads();
        u32 h4[4], ex4[4];
        scan4096(hist, red, tid, h4, ex4);
#pragma unroll 1
        for (int e = 0; e < 8; e++) {
            u64 v = src[e * 1024 + tid];
            unsigned d = (unsigned)(v >> shift) & 15u;
            unsigned m = eqmask4(d);
            unsigned rk = (unsigned)__popc(m & ltm);
            dst[hist[d * 256 + e * 32 + warp] + rk] = v;
        }
        __syncthreads();
        u64* t = src; src = dst; dst = t;
    }
    // 8 passes -> result back in sbufA (== src)

    // ---- softmax over first `budget` entries (arithmetic unchanged) --------
    const float s0 = key2f(~(unsigned)(src[0] >> 32));
    const int budget = g_budget;
    float part = 0.0f;
    float ev[8]; int iv[8];
#pragma unroll
    for (int i = 0; i < 8; i++) {
        int pp = tid + i * 1024;
        u64 v = src[pp];
        unsigned key = ~(unsigned)(v >> 32);
        iv[i] = (int)(v & 0xFFFFFFFFu);
        float e = (pp < budget) ? expf(key2f(key) - s0) : 0.0f;
        ev[i] = e;
        part += e;
    }
#pragma unroll
    for (int o = 16; o > 0; o >>= 1) part += __shfl_down_sync(0xffffffffu, part, o);
    __syncthreads();
    if (lane == 0) fred[64 + warp] = part;
    __syncthreads();
    if (tid == 0) {
        float s = 0.0f;
        for (int w = 0; w < 32; w++) s += fred[64 + w];
        fred[96] = s;
    }
    __syncthreads();
    const float denom = fred[96];

#pragma unroll
    for (int i = 0; i < 8; i++) {
        int pp = tid + i * 1024;
        out_idx[(size_t)row * MAXP + pp] = (float)iv[i];
        out_w  [(size_t)row * MAXP + pp] = ev[i] / denom;
    }
}

// ---------------- launch -----------------------------------------------------
extern "C" void kernel_launch(void* const* d_in, const int* in_sizes, int n_in,
                              void* d_out, int out_size)
{
    const float* x    = (const float*)d_in[0];
    const float* noise= (const float*)d_in[1];
    const float* W1c  = (const float*)d_in[2];
    const float* b1c  = (const float*)d_in[3];
    const float* W2c  = (const float*)d_in[4];
    const float* b2c  = (const float*)d_in[5];
    const float* Ws1  = (const float*)d_in[6];
    const float* bs1  = (const float*)d_in[7];
    const float* Ws2  = (const float*)d_in[8];
    const float* bs2  = (const float*)d_in[9];

    float* out        = (float*)d_out;
    float* out_idx    = out;
    float* out_budget = out + (size_t)BATCH * MAXP;
    float* out_w      = out_budget + 1;
    float* out_comp   = out_w + (size_t)BATCH * MAXP;

    float *hp, *sp;
    cudaGetSymbolAddress((void**)&hp, g_h);
    cudaGetSymbolAddress((void**)&sp, g_scores);

    // fused: h = relu(x@Ws1+bs1)  and  c1 = relu(x@W1c+b1c)  in one wave
    sgemm_fused<<<dim3(9, 16), 256>>>(x, Ws1, bs1, W1c, b1c);
    comp_kernel<<<256, 256>>>(W2c, b2c, out_comp);
    budget_kernel<<<1, 1024>>>(out_budget);

    // scores = h@Ws2 + bs2 + noise*0.1
    sgemm_scores<<<dim3(256, 16), 256>>>(hp, Ws2, bs2, noise, sp);

    // top-k + softmax
    cudaFuncSetAttribute(topk_kernel, cudaFuncAttributeMaxDynamicSharedMemorySize, TOPK_SMEM);
    topk_kernel<<<BATCH, 1024, TOPK_SMEM>>>(out_idx, out_w);
}

// round 4
// speedup vs baseline: 1.1986x; 1.0863x over previous
#include <cuda_runtime.h>
#include <math.h>
#include <stdint.h>

#define BATCH    2048
#define IN_DIM   2048
#define POOLN    32768
#define HIDN     1024
#define MAXP     8192
#define MINP     512

typedef unsigned long long u64;
typedef unsigned int u32;

// ---------------- scratch (device globals: no allocations allowed) ----------
__device__ float g_c1[BATCH * 128];
__device__ float g_h[BATCH * HIDN];
__device__ float g_scores[(size_t)BATCH * POOLN];   // 256 MB
__device__ float g_comp[BATCH];
__device__ int   g_budget;

// ============================================================================
// Double-buffered pipelined GEMM core (scalar FFMA, ascending-k: numerics
// bitwise-frozen vs previous rounds — only staging/buffering changed).
// Tiles: C 128x128 per CTA, k-tile 16, 256 threads, 8x8 per thread.
// ============================================================================
#define GEMM_STS(buf)                                                            \
    As[buf][ca0*4+0][r_a]=ra0.x; As[buf][ca0*4+1][r_a]=ra0.y;                    \
    As[buf][ca0*4+2][r_a]=ra0.z; As[buf][ca0*4+3][r_a]=ra0.w;                    \
    As[buf][ca0*4+4][r_a]=ra1.x; As[buf][ca0*4+5][r_a]=ra1.y;                    \
    As[buf][ca0*4+6][r_a]=ra1.z; As[buf][ca0*4+7][r_a]=ra1.w;                    \
    *(float4*)&Bs[buf][r_b][cb0*4]     = rb0;                                    \
    *(float4*)&Bs[buf][r_b][cb0*4 + 4] = rb1;

#define GEMM_LDG(k0)                                                             \
    {   const float* Ap = Abase + (k0);                                          \
        ra0 = *(const float4*)(Ap + ca0*4);                                      \
        ra1 = *(const float4*)(Ap + ca0*4 + 4);                                  \
        const float* Bp = (Bb) + (size_t)((k0) + r_b) * Nstride;                 \
        rb0 = *(const float4*)(Bp + cb0*4);                                      \
        rb1 = *(const float4*)(Bp + cb0*4 + 4);                                  \
    }

#define GEMM_PIPE(Ab, Bb, KDIM)                                                  \
    float acc[8][8];                                                             \
    _Pragma("unroll")                                                            \
    for (int i = 0; i < 8; i++)                                                  \
        _Pragma("unroll")                                                        \
        for (int j = 0; j < 8; j++) acc[i][j] = 0.0f;                            \
    const int r_a = tid >> 1, ca0 = (tid & 1) * 2;                               \
    const int r_b = tid >> 4, cb0 = (tid & 15) * 2;                              \
    const float* Abase = (Ab) + (size_t)r_a * (KDIM);                            \
    float4 ra0, ra1, rb0, rb1;                                                   \
    GEMM_LDG(0)                                                                  \
    GEMM_STS(0)                                                                  \
    __syncthreads();                                                             \
    const int ITERS = (KDIM) / 16;                                               \
    for (int it = 0; it < ITERS; it++) {                                         \
        const int cur = it & 1;                                                  \
        if (it + 1 < ITERS) { GEMM_LDG((it + 1) * 16) }                          \
        _Pragma("unroll")                                                        \
        for (int k = 0; k < 16; k++) {                                           \
            float a[8], b[8];                                                    \
            const float4* a4 = (const float4*)&As[cur][k][tm * 8];               \
            const float4* b4 = (const float4*)&Bs[cur][k][tn * 8];               \
            float4 av0 = a4[0], av1 = a4[1];                                     \
            float4 bv0 = b4[0], bv1 = b4[1];                                     \
            a[0]=av0.x; a[1]=av0.y; a[2]=av0.z; a[3]=av0.w;                      \
            a[4]=av1.x; a[5]=av1.y; a[6]=av1.z; a[7]=av1.w;                      \
            b[0]=bv0.x; b[1]=bv0.y; b[2]=bv0.z; b[3]=bv0.w;                      \
            b[4]=bv1.x; b[5]=bv1.y; b[6]=bv1.z; b[7]=bv1.w;                      \
            _Pragma("unroll")                                                    \
            for (int i = 0; i < 8; i++)                                          \
                _Pragma("unroll")                                                \
                for (int j = 0; j < 8; j++) acc[i][j] += a[i] * b[j];            \
        }                                                                        \
        if (it + 1 < ITERS) { GEMM_STS(cur ^ 1) }                                \
        __syncthreads();                                                         \
    }

// ---------------- Ws2 GEMM: scores = h @ Ws2 + bs2 + noise*0.1 --------------
__global__ void __launch_bounds__(256, 2) sgemm_scores(
    const float* __restrict__ A, const float* __restrict__ B,
    const float* __restrict__ bias, const float* __restrict__ noise,
    float* __restrict__ C)
{
    __shared__ float As[2][16][128];
    __shared__ float Bs[2][16][128];
    const int bx = blockIdx.x, by = blockIdx.y;
    const int tid = threadIdx.x;
    const int tn = tid & 15, tm = tid >> 4;
    const int Nstride = POOLN;
    const float* Ab = A + (size_t)by * 128 * HIDN;
    const float* Bb = B + (size_t)bx * 128;

    GEMM_PIPE(Ab, Bb, HIDN)

    const int col0 = bx * 128 + tn * 8;
    const float4 bi0 = *(const float4*)&bias[col0];
    const float4 bi1 = *(const float4*)&bias[col0 + 4];
#pragma unroll
    for (int i = 0; i < 8; i++) {
        const int row = by * 128 + tm * 8 + i;
        const float* np = noise + (size_t)row * POOLN + col0;
        float4 n0 = *(const float4*)np;
        float4 n1 = *(const float4*)(np + 4);
        float4 o0, o1;
        o0.x = __fadd_rn(__fadd_rn(acc[i][0], bi0.x), __fmul_rn(n0.x, 0.1f));
        o0.y = __fadd_rn(__fadd_rn(acc[i][1], bi0.y), __fmul_rn(n0.y, 0.1f));
        o0.z = __fadd_rn(__fadd_rn(acc[i][2], bi0.z), __fmul_rn(n0.z, 0.1f));
        o0.w = __fadd_rn(__fadd_rn(acc[i][3], bi0.w), __fmul_rn(n0.w, 0.1f));
        o1.x = __fadd_rn(__fadd_rn(acc[i][4], bi1.x), __fmul_rn(n1.x, 0.1f));
        o1.y = __fadd_rn(__fadd_rn(acc[i][5], bi1.y), __fmul_rn(n1.y, 0.1f));
        o1.z = __fadd_rn(__fadd_rn(acc[i][6], bi1.z), __fmul_rn(n1.z, 0.1f));
        o1.w = __fadd_rn(__fadd_rn(acc[i][7], bi1.w), __fmul_rn(n1.w, 0.1f));
        float* cp = C + (size_t)row * POOLN + col0;
        *(float4*)cp = o0;
        *(float4*)(cp + 4) = o1;
    }
}

// ---------------- fused Ws1 + W1c GEMM: relu(x@W + b) -----------------------
// bx in [0,8): h tile (N=1024).  bx == 8: c1 tile (N=128).
__global__ void __launch_bounds__(256, 2) sgemm_fused(
    const float* __restrict__ x,
    const float* __restrict__ Ws1, const float* __restrict__ bs1,
    const float* __restrict__ W1c, const float* __restrict__ b1c)
{
    __shared__ float As[2][16][128];
    __shared__ float Bs[2][16][128];
    const int bx = blockIdx.x, by = blockIdx.y;
    const int tid = threadIdx.x;
    const int tn = tid & 15, tm = tid >> 4;

    const bool is_c1 = (bx == 8);
    const float* Bsel = is_c1 ? W1c : Ws1;
    const float* bias = is_c1 ? b1c : bs1;
    float*       Csel = is_c1 ? g_c1 : g_h;
    const int Nstride = is_c1 ? 128 : HIDN;
    const int cb      = is_c1 ? 0 : bx * 128;

    const float* Ab = x + (size_t)by * 128 * IN_DIM;
    const float* Bb = Bsel + cb;

    GEMM_PIPE(Ab, Bb, IN_DIM)

    const int col0 = cb + tn * 8;
    const float4 bi0 = *(const float4*)&bias[tn * 8];
    const float4 bi1 = *(const float4*)&bias[tn * 8 + 4];
    (void)col0;
#pragma unroll
    for (int i = 0; i < 8; i++) {
        const int row = by * 128 + tm * 8 + i;
        float4 o0, o1;
        o0.x = fmaxf(__fadd_rn(acc[i][0], bi0.x), 0.0f);
        o0.y = fmaxf(__fadd_rn(acc[i][1], bi0.y), 0.0f);
        o0.z = fmaxf(__fadd_rn(acc[i][2], bi0.z), 0.0f);
        o0.w = fmaxf(__fadd_rn(acc[i][3], bi0.w), 0.0f);
        o1.x = fmaxf(__fadd_rn(acc[i][4], bi1.x), 0.0f);
        o1.y = fmaxf(__fadd_rn(acc[i][5], bi1.y), 0.0f);
        o1.z = fmaxf(__fadd_rn(acc[i][6], bi1.z), 0.0f);
        o1.w = fmaxf(__fadd_rn(acc[i][7], bi1.w), 0.0f);
        float* cp = Csel + (size_t)row * Nstride + cb + tn * 8;
        *(float4*)cp = o0;
        *(float4*)(cp + 4) = o1;
    }
}

// ---------------- comp stage 2: sigmoid(c1 @ W2c + b2c) ---------------------
__global__ void comp_kernel(const float* __restrict__ W2c,
                            const float* __restrict__ b2c,
                            float* __restrict__ out_comp)
{
    int row  = blockIdx.x * 8 + (threadIdx.x >> 5);
    int lane = threadIdx.x & 31;
    float p = 0.0f;
#pragma unroll
    for (int t = lane; t < 128; t += 32) p += g_c1[row * 128 + t] * W2c[t];
#pragma unroll
    for (int o = 16; o > 0; o >>= 1) p += __shfl_down_sync(0xffffffffu, p, o);
    if (lane == 0) {
        float z = p + b2c[0];
        float c = 1.0f / (1.0f + expf(-z));
        g_comp[row]  = c;
        out_comp[row] = c;
    }
}

// ---------------- budget ----------------------------------------------------
__global__ void budget_kernel(float* __restrict__ out_budget)
{
    __shared__ float ws[32];
    int tid = threadIdx.x;
    float s = g_comp[tid] + g_comp[tid + 1024];
#pragma unroll
    for (int o = 16; o > 0; o >>= 1) s += __shfl_down_sync(0xffffffffu, s, o);
    if ((tid & 31) == 0) ws[tid >> 5] = s;
    __syncthreads();
    if (tid < 32) {
        float v = ws[tid];
#pragma unroll
        for (int o = 16; o > 0; o >>= 1) v += __shfl_down_sync(0xffffffffu, v, o);
        if (tid == 0) {
            float mean  = v / 2048.0f;
            float scale = mean * mean;                 // EXP = 2.0
            float t = 512.0f + 7680.0f * scale;
            int b = (int)floorf(t);
            if (b < MINP) b = MINP;
            if (b > MAXP) b = MAXP;
            g_budget = b;
            out_budget[0] = (float)b;
        }
    }
}

// ============================================================================
// top-k + softmax  (unchanged from R3)
// ============================================================================
__device__ __forceinline__ unsigned f2key(float s) {
    unsigned b = __float_as_uint(s);
    return (b & 0x80000000u) ? ~b : (b | 0x80000000u);   // order-preserving
}
__device__ __forceinline__ float key2f(unsigned k) {
    return __uint_as_float((k & 0x80000000u) ? (k ^ 0x80000000u) : ~k);
}

#define OFF_KEYS   0
#define OFF_SBUFA  131072
#define OFF_HIST   196608
#define OFF_RED    212992
#define TOPK_SMEM  (212992 + 640)

__device__ __forceinline__ u32 scan4096(u32* a, u32* red, int tid,
                                        u32 h[4], u32 ex[4])
{
    const int lane = tid & 31, warp = tid >> 5;
#pragma unroll
    for (int i = 0; i < 4; i++) h[i] = a[tid * 4 + i];
    u32 s = h[0] + h[1] + h[2] + h[3];
    u32 inc = s;
#pragma unroll
    for (int o = 1; o < 32; o <<= 1) {
        u32 n = __shfl_up_sync(0xffffffffu, inc, o);
        if (lane >= o) inc += n;
    }
    if (lane == 31) red[warp] = inc;
    __syncthreads();
    if (tid < 32) {
        u32 v = red[tid];
#pragma unroll
        for (int o = 1; o < 32; o <<= 1) {
            u32 n = __shfl_up_sync(0xffffffffu, v, o);
            if (tid >= o) v += n;
        }
        red[32 + tid] = v;
    }
    __syncthreads();
    u32 wb = (warp == 0) ? 0u : red[32 + warp - 1];
    u32 tb = wb + inc - s;
    ex[0] = tb; ex[1] = ex[0] + h[0]; ex[2] = ex[1] + h[1]; ex[3] = ex[2] + h[2];
#pragma unroll
    for (int i = 0; i < 4; i++) a[tid * 4 + i] = ex[i];
    u32 total = red[32 + 31];
    __syncthreads();
    return total;
}

__device__ __forceinline__ unsigned eqmask4(unsigned d) {
    unsigned m = 0xffffffffu;
#pragma unroll
    for (int b = 0; b < 4; b++) {
        unsigned bal = __ballot_sync(0xffffffffu, (d >> b) & 1u);
        m &= ((d >> b) & 1u) ? bal : ~bal;
    }
    return m;
}

__global__ void __launch_bounds__(1024) topk_kernel(
    float* __restrict__ out_idx, float* __restrict__ out_w)
{
    extern __shared__ unsigned char smem_raw[];
    u32* keys  = (u32*)(smem_raw + OFF_KEYS);
    u64* sbufA = (u64*)(smem_raw + OFF_SBUFA);
    u64* sbufB = (u64*)(smem_raw + OFF_KEYS);     // alias: valid after keys dead
    u32* hist  = (u32*)(smem_raw + OFF_HIST);
    u32* red   = (u32*)(smem_raw + OFF_RED);
    float* fred = (float*)red;

    const int row = blockIdx.x;
    const int tid = threadIdx.x;
    const int warp = tid >> 5, lane = tid & 31;
    const unsigned ltm = (1u << lane) - 1u;
    const float* srow = g_scores + (size_t)row * POOLN;

    for (int j = tid; j < POOLN; j += 1024) keys[j] = f2key(srow[j]);
    __syncthreads();

    // ---- exact k-th largest key via 3-level radix histogram (12/12/8) ----
    unsigned prefix = 0;
    u32 base_gt = 0;
#pragma unroll
    for (int lvl = 0; lvl < 3; lvl++) {
        const int lb   = (lvl < 2) ? 12 : 8;
        const int done = (lvl == 0) ? 0 : (lvl == 1 ? 12 : 24);
#pragma unroll
        for (int i = 0; i < 4; i++) hist[tid * 4 + i] = 0;
        __syncthreads();
        for (int j = tid; j < POOLN; j += 1024) {
            u32 k = keys[j];
            bool part = (done == 0) || ((k >> (32 - done)) == prefix);
            unsigned d = part ? ((k << done) >> (32 - lb)) : 0xFFFFFFFFu;
            unsigned m = __match_any_sync(0xffffffffu, d);
            if (part && (m & ltm) == 0)
                atomicAdd(&hist[d], __popc(m));
        }
        __syncthreads();
        u32 h4[4], ex4[4];
        u32 T = scan4096(hist, red, tid, h4, ex4);
#pragma unroll
        for (int i = 0; i < 4; i++) {
            u32 cg = T - ex4[i] - h4[i];
            if (h4[i] && base_gt + cg < MAXP && base_gt + cg + h4[i] >= MAXP) {
                red[140] = (u32)(tid * 4 + i);
                red[141] = cg;
            }
        }
        __syncthreads();
        prefix = (prefix << lb) | red[140];
        base_gt += red[141];
        __syncthreads();
    }
    const unsigned V = prefix;

    // ---- stable compaction ----
    const int beg = tid * 32;
    int cgt = 0, ceq = 0;
#pragma unroll 8
    for (int j = beg; j < beg + 32; j++) {
        unsigned k = keys[j];
        cgt += (k > V); ceq += (k == V);
    }
    int vg = cgt, ve = ceq;
#pragma unroll
    for (int o = 1; o < 32; o <<= 1) {
        int ng = __shfl_up_sync(0xffffffffu, vg, o);
        int ne = __shfl_up_sync(0xffffffffu, ve, o);
        if (lane >= o) { vg += ng; ve += ne; }
    }
    if (lane == 31) { red[2 + warp] = (u32)vg; red[34 + warp] = (u32)ve; }
    __syncthreads();
    if (tid < 32) {
        int wg = (int)red[2 + tid], we = (int)red[34 + tid];
#pragma unroll
        for (int o = 1; o < 32; o <<= 1) {
            int ng = __shfl_up_sync(0xffffffffu, wg, o);
            int ne = __shfl_up_sync(0xffffffffu, we, o);
            if (tid >= o) { wg += ng; we += ne; }
        }
        red[2 + tid] = (u32)wg; red[34 + tid] = (u32)we;
    }
    __syncthreads();
    int bgt = vg - cgt + (warp ? (int)red[2 + warp - 1] : 0);
    int beq = ve - ceq + (warp ? (int)red[34 + warp - 1] : 0);
    const int count_gt = (int)red[2 + 31];
    const int need_eq  = MAXP - count_gt;

    for (int j = beg; j < beg + 32; j++) {
        unsigned k = keys[j];
        if (k > V) {
            sbufA[bgt++] = ((u64)(~k) << 32) | (unsigned)j;
        } else if (k == V) {
            int r = beq++;
            if (r < need_eq)
                sbufA[count_gt + r] = ((u64)(~V) << 32) | (unsigned)j;
        }
    }
    __syncthreads();

    // ---- stable LSD radix sort: 8 x 4-bit on ~key ----
    u64* src = sbufA;
    u64* dst = sbufB;
#pragma unroll 1
    for (int p = 0; p < 8; p++) {
        const int shift = 32 + 4 * p;
#pragma unroll
        for (int i = 0; i < 4; i++) hist[tid * 4 + i] = 0;
        __syncthreads();
#pragma unroll 1
        for (int e = 0; e < 8; e++) {
            u64 v = src[e * 1024 + tid];
            unsigned d = (unsigned)(v >> shift) & 15u;
            unsigned m = eqmask4(d);
            if ((m & ltm) == 0)
                hist[d * 256 + e * 32 + warp] = (u32)__popc(m);
        }
        __syncthreads();
        u32 h4[4], ex4[4];
        scan4096(hist, red, tid, h4, ex4);
#pragma unroll 1
        for (int e = 0; e < 8; e++) {
            u64 v = src[e * 1024 + tid];
            unsigned d = (unsigned)(v >> shift) & 15u;
            unsigned m = eqmask4(d);
            unsigned rk = (unsigned)__popc(m & ltm);
            dst[hist[d * 256 + e * 32 + warp] + rk] = v;
        }
        __syncthreads();
        u64* t = src; src = dst; dst = t;
    }

    // ---- softmax over first `budget` entries ----
    const float s0 = key2f(~(unsigned)(src[0] >> 32));
    const int budget = g_budget;
    float part = 0.0f;
    float ev[8]; int iv[8];
#pragma unroll
    for (int i = 0; i < 8; i++) {
        int pp = tid + i * 1024;
        u64 v = src[pp];
        unsigned key = ~(unsigned)(v >> 32);
        iv[i] = (int)(v & 0xFFFFFFFFu);
        float e = (pp < budget) ? expf(key2f(key) - s0) : 0.0f;
        ev[i] = e;
        part += e;
    }
#pragma unroll
    for (int o = 16; o > 0; o >>= 1) part += __shfl_down_sync(0xffffffffu, part, o);
    __syncthreads();
    if (lane == 0) fred[64 + warp] = part;
    __syncthreads();
    if (tid == 0) {
        float s = 0.0f;
        for (int w = 0; w < 32; w++) s += fred[64 + w];
        fred[96] = s;
    }
    __syncthreads();
    const float denom = fred[96];

#pragma unroll
    for (int i = 0; i < 8; i++) {
        int pp = tid + i * 1024;
        out_idx[(size_t)row * MAXP + pp] = (float)iv[i];
        out_w  [(size_t)row * MAXP + pp] = ev[i] / denom;
    }
}

// ---------------- launch -----------------------------------------------------
extern "C" void kernel_launch(void* const* d_in, const int* in_sizes, int n_in,
                              void* d_out, int out_size)
{
    const float* x    = (const float*)d_in[0];
    const float* noise= (const float*)d_in[1];
    const float* W1c  = (const float*)d_in[2];
    const float* b1c  = (const float*)d_in[3];
    const float* W2c  = (const float*)d_in[4];
    const float* b2c  = (const float*)d_in[5];
    const float* Ws1  = (const float*)d_in[6];
    const float* bs1  = (const float*)d_in[7];
    const float* Ws2  = (const float*)d_in[8];
    const float* bs2  = (const float*)d_in[9];

    float* out        = (float*)d_out;
    float* out_idx    = out;
    float* out_budget = out + (size_t)BATCH * MAXP;
    float* out_w      = out_budget + 1;
    float* out_comp   = out_w + (size_t)BATCH * MAXP;

    float *hp, *sp;
    cudaGetSymbolAddress((void**)&hp, g_h);
    cudaGetSymbolAddress((void**)&sp, g_scores);

    // fused: h = relu(x@Ws1+bs1)  and  c1 = relu(x@W1c+b1c)  in one wave
    sgemm_fused<<<dim3(9, 16), 256>>>(x, Ws1, bs1, W1c, b1c);
    comp_kernel<<<256, 256>>>(W2c, b2c, out_comp);
    budget_kernel<<<1, 1024>>>(out_budget);

    // scores = h@Ws2 + bs2 + noise*0.1
    sgemm_scores<<<dim3(256, 16), 256>>>(hp, Ws2, bs2, noise, sp);

    // top-k + softmax
    cudaFuncSetAttribute(topk_kernel, cudaFuncAttributeMaxDynamicSharedMemorySize, TOPK_SMEM);
    topk_kernel<<<BATCH, 1024, TOPK_SMEM>>>(out_idx, out_w);
}